// round 1
// baseline (speedup 1.0000x reference)
#include <cuda_runtime.h>
#include <cstddef>

// Problem constants (fixed by the reference)
#define NN 100000
#define HH 512
#define EE 160000
#define BN_EPS 1e-5f
#define SLOPE 0.01f

// ---------------- scratch (no cudaMalloc allowed) ----------------
__device__ float g_A[(size_t)NN * HH];   // current node features
__device__ float g_B[(size_t)NN * HH];   // h @ Wc
__device__ float g_dinv[NN];
__device__ int   g_deg[NN];
__device__ float g_colsum[HH];
__device__ float g_colsq[HH];
__device__ float g_scale[HH];
__device__ float g_shift[HH];
__device__ float g_weff[HH + 1];         // [0..511] = W2@WO, [512] = b2.WO + bO
__device__ int   g_is64;                 // edge_index stored as int64?

// ---------------- packed fp32x2 helpers (FFMA2 = full-rate fp32 on sm_10x) ---
__device__ __forceinline__ unsigned long long pack2(float lo, float hi) {
    unsigned long long r;
    asm("mov.b64 %0, {%1, %2};" : "=l"(r)
        : "r"(__float_as_uint(lo)), "r"(__float_as_uint(hi)));
    return r;
}
__device__ __forceinline__ unsigned long long fma2(unsigned long long a,
                                                   unsigned long long b,
                                                   unsigned long long c) {
    unsigned long long d;
    asm("fma.rn.f32x2 %0, %1, %2, %3;" : "=l"(d) : "l"(a), "l"(b), "l"(c));
    return d;
}
__device__ __forceinline__ void unpack2(unsigned long long v, float& lo, float& hi) {
    unsigned int a, b;
    asm("mov.b64 {%0, %1}, %2;" : "=r"(a), "=r"(b) : "l"(v));
    lo = __uint_as_float(a);
    hi = __uint_as_float(b);
}

// ---------------- setup kernels ----------------
__global__ void k_prep(const int* __restrict__ ei) {
    int i = blockIdx.x * blockDim.x + threadIdx.x;
    if (i == 0) {
        // int64 little-endian node ids < 2^31 -> all odd int32 words are 0
        g_is64 = ((ei[1] | ei[3] | ei[5] | ei[7] | ei[9]) == 0) ? 1 : 0;
    }
    if (i < NN) g_deg[i] = 0;
}

__global__ void k_deg(const int* __restrict__ ei) {
    int e = blockIdx.x * blockDim.x + threadIdx.x;
    if (e >= EE) return;
    int is64 = g_is64;
    int dst = is64 ? ei[2 * EE + 2 * e] : ei[EE + e];
    atomicAdd(&g_deg[dst], 1);
}

__global__ void k_dinv() {
    int i = blockIdx.x * blockDim.x + threadIdx.x;
    if (i < NN) g_dinv[i] = rsqrtf((float)g_deg[i] + 1.0f);
}

// ---------------- SGEMM: C[NN,512] = A[NN,512] @ W[512,512] (+bias) --------
// 128x128 block tile, BK=16, 256 threads, 8x8 per thread, FFMA2 accumulators.
__global__ __launch_bounds__(256)
void k_gemm(const float* __restrict__ A, const float* __restrict__ W,
            const float* __restrict__ bias, float* __restrict__ C) {
    __shared__ float As[16][132];   // [k][m], padded stride to spread banks
    __shared__ float Ws[16][128];   // [k][n]

    const int tid = threadIdx.x;
    const int bm = blockIdx.x * 128;
    const int bn = blockIdx.y * 128;
    const int tx = tid & 15;        // 0..15 -> 8 output cols each
    const int ty = tid >> 4;        // 0..15 -> 8 output rows each

    unsigned long long acc[8][4];
#pragma unroll
    for (int i = 0; i < 8; i++)
#pragma unroll
        for (int j = 0; j < 4; j++) acc[i][j] = 0ULL;  // two packed +0.0f

    for (int k0 = 0; k0 < 512; k0 += 16) {
        // load A tile 128x16 (512 float4, 2 per thread), store transposed
#pragma unroll
        for (int l = 0; l < 2; l++) {
            int i = tid + l * 256;
            int r = i >> 2;
            int c4 = (i & 3) * 4;
            int grow = bm + r;
            float4 v = make_float4(0.f, 0.f, 0.f, 0.f);
            if (grow < NN)
                v = *(const float4*)(A + (size_t)grow * 512 + k0 + c4);
            As[c4 + 0][r] = v.x;
            As[c4 + 1][r] = v.y;
            As[c4 + 2][r] = v.z;
            As[c4 + 3][r] = v.w;
        }
        // load W tile 16x128 (512 float4, 2 per thread), contiguous
#pragma unroll
        for (int l = 0; l < 2; l++) {
            int i = tid + l * 256;
            int r = i >> 5;
            int c4 = (i & 31) * 4;
            *(float4*)&Ws[r][c4] =
                *(const float4*)(W + (size_t)(k0 + r) * 512 + bn + c4);
        }
        __syncthreads();

#pragma unroll
        for (int kk = 0; kk < 16; kk++) {
            float a[8], b[8];
            *(float4*)&a[0] = *(const float4*)&As[kk][ty * 8];
            *(float4*)&a[4] = *(const float4*)&As[kk][ty * 8 + 4];
            *(float4*)&b[0] = *(const float4*)&Ws[kk][tx * 8];
            *(float4*)&b[4] = *(const float4*)&Ws[kk][tx * 8 + 4];
            unsigned long long bp[4];
            bp[0] = pack2(b[0], b[1]);
            bp[1] = pack2(b[2], b[3]);
            bp[2] = pack2(b[4], b[5]);
            bp[3] = pack2(b[6], b[7]);
#pragma unroll
            for (int i = 0; i < 8; i++) {
                unsigned long long ap = pack2(a[i], a[i]);
#pragma unroll
                for (int j = 0; j < 4; j++) acc[i][j] = fma2(ap, bp[j], acc[i][j]);
            }
        }
        __syncthreads();
    }

    // epilogue
    const int gcol = bn + tx * 8;
    float bs[8];
#pragma unroll
    for (int t = 0; t < 8; t++) bs[t] = bias ? bias[gcol + t] : 0.0f;

#pragma unroll
    for (int i = 0; i < 8; i++) {
        int grow = bm + ty * 8 + i;
        if (grow >= NN) continue;
        float o[8];
#pragma unroll
        for (int j = 0; j < 4; j++) unpack2(acc[i][j], o[2 * j], o[2 * j + 1]);
#pragma unroll
        for (int t = 0; t < 8; t++) o[t] += bs[t];
        *(float4*)(C + (size_t)grow * 512 + gcol) =
            make_float4(o[0], o[1], o[2], o[3]);
        *(float4*)(C + (size_t)grow * 512 + gcol + 4) =
            make_float4(o[4], o[5], o[6], o[7]);
    }
}

// ---------------- aggregation ----------------
// A[i,:] = dinv[i]^2 * B[i,:] + bc   (self-loop + bias init)
__global__ void k_agg_init(const float4* __restrict__ B4, float4* __restrict__ A4,
                           const float4* __restrict__ bc4) {
    int i = blockIdx.x * blockDim.x + threadIdx.x;   // over NN*HH/4 = 12.8M
    if (i >= NN * (HH / 4)) return;
    int row = i / (HH / 4);
    int c = i & (HH / 4 - 1);
    float d = g_dinv[row];
    d = d * d;
    float4 v = B4[i];
    float4 b = bc4[c];
    float4 o;
    o.x = fmaf(d, v.x, b.x);
    o.y = fmaf(d, v.y, b.y);
    o.z = fmaf(d, v.z, b.z);
    o.w = fmaf(d, v.w, b.w);
    A4[i] = o;
}

// per-edge scatter: A[dst,:] += dinv[src]*dinv[dst] * B[src,:]
__global__ void k_scatter(const int* __restrict__ ei, const float* __restrict__ B,
                          float* __restrict__ A) {
    int g = blockIdx.x * blockDim.x + threadIdx.x;   // EE * 128 = 20.48M
    if (g >= EE * (HH / 4)) return;
    int e = g >> 7;
    int j = (g & 127) << 2;
    int is64 = g_is64;
    int src = is64 ? ei[2 * e] : ei[e];
    int dst = is64 ? ei[2 * EE + 2 * e] : ei[EE + e];
    float w = g_dinv[src] * g_dinv[dst];
    float4 v = *(const float4*)(B + (size_t)src * HH + j);
    float* out = A + (size_t)dst * HH + j;
    atomicAdd(out + 0, w * v.x);
    atomicAdd(out + 1, w * v.y);
    atomicAdd(out + 2, w * v.z);
    atomicAdd(out + 3, w * v.w);
}

// ---------------- batchnorm ----------------
__global__ void k_bnzero() {
    int i = threadIdx.x;
    g_colsum[i] = 0.f;
    g_colsq[i] = 0.f;
}

__global__ void k_bn_stats(const float* __restrict__ A) {
    int c = threadIdx.x;   // 256 threads: cols c and c+256
    float s0 = 0.f, q0 = 0.f, s1 = 0.f, q1 = 0.f;
    for (int r = blockIdx.x; r < NN; r += gridDim.x) {
        const float* row = A + (size_t)r * HH;
        float v0 = row[c];
        float v1 = row[c + 256];
        s0 += v0; q0 += v0 * v0;
        s1 += v1; q1 += v1 * v1;
    }
    atomicAdd(&g_colsum[c], s0);
    atomicAdd(&g_colsq[c], q0);
    atomicAdd(&g_colsum[c + 256], s1);
    atomicAdd(&g_colsq[c + 256], q1);
}

__global__ void k_bn_final(const float* __restrict__ gamma,
                           const float* __restrict__ beta) {
    int c = threadIdx.x;
    float inv_n = 1.0f / (float)NN;
    float mean = g_colsum[c] * inv_n;
    float var = g_colsq[c] * inv_n - mean * mean;
    float sc = gamma[c] * rsqrtf(var + BN_EPS);
    g_scale[c] = sc;
    g_shift[c] = beta[c] - mean * sc;
}

__global__ void k_bn_apply(float4* __restrict__ A4) {
    int i = blockIdx.x * blockDim.x + threadIdx.x;
    if (i >= NN * (HH / 4)) return;
    int c = (i & (HH / 4 - 1)) << 2;
    float4 v = A4[i];
    float x0 = g_scale[c + 0] * v.x + g_shift[c + 0];
    float x1 = g_scale[c + 1] * v.y + g_shift[c + 1];
    float x2 = g_scale[c + 2] * v.z + g_shift[c + 2];
    float x3 = g_scale[c + 3] * v.w + g_shift[c + 3];
    v.x = (x0 >= 0.f) ? x0 : SLOPE * x0;
    v.y = (x1 >= 0.f) ? x1 : SLOPE * x1;
    v.z = (x2 >= 0.f) ? x2 : SLOPE * x2;
    v.w = (x3 >= 0.f) ? x3 : SLOPE * x3;
    A4[i] = v;
}

// ---------------- fused tail: w_eff = W2@WO, c_eff = b2.WO + bO -----------
__global__ void k_weff(const float* __restrict__ W2, const float* __restrict__ b2,
                       const float* __restrict__ WO, const float* __restrict__ bO) {
    int b = blockIdx.x;   // 0..512 inclusive
    const float* rowp = (b < HH) ? (W2 + (size_t)b * HH) : b2;
    float s = 0.f;
    for (int j = threadIdx.x; j < HH; j += 256) s += rowp[j] * WO[j];
#pragma unroll
    for (int o = 16; o; o >>= 1) s += __shfl_xor_sync(0xffffffffu, s, o);
    __shared__ float red[8];
    if ((threadIdx.x & 31) == 0) red[threadIdx.x >> 5] = s;
    __syncthreads();
    if (threadIdx.x == 0) {
        float t = 0.f;
        for (int i = 0; i < 8; i++) t += red[i];
        g_weff[b] = (b < HH) ? t : (t + bO[0]);
    }
}

// out[i] = sigmoid(dot(A[i,:], w_eff) + c_eff), one warp per row
__global__ void k_out(const float* __restrict__ A, float* __restrict__ out) {
    int w = (blockIdx.x * blockDim.x + threadIdx.x) >> 5;
    int lane = threadIdx.x & 31;
    if (w >= NN) return;
    const float4* row = (const float4*)(A + (size_t)w * HH);
    const float4* wf = (const float4*)g_weff;
    float s = 0.f;
#pragma unroll
    for (int i = 0; i < 4; i++) {
        float4 a = row[lane + 32 * i];
        float4 b = wf[lane + 32 * i];
        s += a.x * b.x + a.y * b.y + a.z * b.z + a.w * b.w;
    }
#pragma unroll
    for (int o = 16; o; o >>= 1) s += __shfl_xor_sync(0xffffffffu, s, o);
    if (lane == 0) {
        float t = s + g_weff[HH];
        out[w] = 1.0f / (1.0f + expf(-t));
    }
}

// ---------------- launcher ----------------
extern "C" void kernel_launch(void* const* d_in, const int* in_sizes, int n_in,
                              void* d_out, int out_size) {
    const float* x     = (const float*)d_in[0];
    const int*   ei    = (const int*)d_in[1];
    const float* W1    = (const float*)d_in[2];
    const float* b1    = (const float*)d_in[3];
    const float* Wc    = (const float*)d_in[4];
    const float* bc    = (const float*)d_in[5];
    const float* gamma = (const float*)d_in[6];
    const float* beta  = (const float*)d_in[7];
    const float* W2    = (const float*)d_in[8];
    const float* b2    = (const float*)d_in[9];
    const float* WO    = (const float*)d_in[10];
    const float* bO    = (const float*)d_in[11];
    float* out = (float*)d_out;

    float *pA, *pB;
    cudaGetSymbolAddress((void**)&pA, g_A);
    cudaGetSymbolAddress((void**)&pB, g_B);

    k_prep<<<(NN + 255) / 256, 256>>>(ei);
    k_deg<<<(EE + 255) / 256, 256>>>(ei);
    k_dinv<<<(NN + 255) / 256, 256>>>();

    dim3 gg((NN + 127) / 128, 4);
    // h = x @ W1 + b1
    k_gemm<<<gg, 256>>>(x, W1, b1, pA);

    const int elem4 = NN * (HH / 4);          // 12.8M
    const int edge4 = EE * (HH / 4);          // 20.48M
    for (int layer = 0; layer < 2; layer++) {
        k_gemm<<<gg, 256>>>(pA, Wc, nullptr, pB);                 // B = h@Wc
        k_agg_init<<<(elem4 + 255) / 256, 256>>>(
            (const float4*)pB, (float4*)pA, (const float4*)bc);   // self + bias
        k_scatter<<<(edge4 + 255) / 256, 256>>>(ei, pB, pA);      // neighbor msgs
        k_bnzero<<<1, 512>>>();
        k_bn_stats<<<2048, 256>>>(pA);
        k_bn_final<<<1, 512>>>(gamma, beta);
        k_bn_apply<<<(elem4 + 255) / 256, 256>>>((float4*)pA);    // BN + LeakyReLU
    }

    k_weff<<<HH + 1, 256>>>(W2, b2, WO, bO);
    k_out<<<(NN * 32 + 255) / 256, 256>>>(pA, out);
}

// round 3
// speedup vs baseline: 1.7678x; 1.7678x over previous
#include <cuda_runtime.h>
#include <cuda_bf16.h>
#include <cstdint>
#include <cstddef>

// Problem constants (fixed by the reference)
#define NN 100000
#define HH 512
#define EE 160000
#define BN_EPS 1e-5f
#define SLOPE 0.01f

// ---------------- scratch (no cudaMalloc allowed) ----------------
__device__ float g_A[(size_t)NN * HH];   // current node features
__device__ float g_B[(size_t)NN * HH];   // h @ Wc
__device__ float g_dinv[NN];
__device__ int   g_deg[NN];
__device__ float g_colsum[HH];
__device__ float g_colsq[HH];
__device__ float g_scale[HH];
__device__ float g_shift[HH];
__device__ float g_weff[HH + 1];         // [0..511] = W2@WO, [512] = b2.WO + bO
__device__ int   g_is64;                 // edge_index stored as int64?

// transposed + hi/lo-split weights: T[n][k] = bf16(W[k][n]), residual in l
__device__ __nv_bfloat16 g_w1h[HH * HH];
__device__ __nv_bfloat16 g_w1l[HH * HH];
__device__ __nv_bfloat16 g_wch[HH * HH];
__device__ __nv_bfloat16 g_wcl[HH * HH];

// ---------------- setup kernels ----------------
__global__ void k_prep(const int* __restrict__ ei) {
    int i = blockIdx.x * blockDim.x + threadIdx.x;
    if (i == 0)
        g_is64 = ((ei[1] | ei[3] | ei[5] | ei[7] | ei[9]) == 0) ? 1 : 0;
    if (i < NN) g_deg[i] = 0;
}

__global__ void k_deg(const int* __restrict__ ei) {
    int e = blockIdx.x * blockDim.x + threadIdx.x;
    if (e >= EE) return;
    int is64 = g_is64;
    int dst = is64 ? ei[2 * EE + 2 * e] : ei[EE + e];
    atomicAdd(&g_deg[dst], 1);
}

__global__ void k_dinv() {
    int i = blockIdx.x * blockDim.x + threadIdx.x;
    if (i < NN) g_dinv[i] = rsqrtf((float)g_deg[i] + 1.0f);
}

// Transpose + hi/lo bf16 split: T[n][k] = split(W[k][n])
__global__ void k_conv_w(const float* __restrict__ W, __nv_bfloat16* __restrict__ Th,
                         __nv_bfloat16* __restrict__ Tl) {
    int k = blockIdx.x;
    for (int n = threadIdx.x; n < HH; n += blockDim.x) {
        float f = W[(size_t)k * HH + n];
        __nv_bfloat16 h = __float2bfloat16(f);
        float r = f - __bfloat162float(h);
        Th[(size_t)n * HH + k] = h;
        Tl[(size_t)n * HH + k] = __float2bfloat16(r);
    }
}

// ---------------- tensor-core GEMM via mma.sync (compute_100-safe) ---------
// C[NN,512] = A[NN,512] @ W[512,512] (+bias); W given pre-transposed & split.
// CTA: 128x128 tile, BK=32, 8 warps (2m x 4n), warp tile 64x32.
#define BM 128
#define BNT 128
#define BK 32
#define NCHUNK (HH / BK)     // 16
#define PADK 40              // padded smem row (bf16 elems): conflict-free LDSM

__device__ __forceinline__ void ldsm_x4(uint32_t* r, uint32_t addr) {
    asm volatile("ldmatrix.sync.aligned.m8n8.x4.shared.b16 {%0,%1,%2,%3}, [%4];"
                 : "=r"(r[0]), "=r"(r[1]), "=r"(r[2]), "=r"(r[3]) : "r"(addr));
}
__device__ __forceinline__ void mma_bf16(float* d, const uint32_t* a,
                                         const uint32_t* b) {
    asm volatile(
        "mma.sync.aligned.m16n8k16.row.col.f32.bf16.bf16.f32 "
        "{%0,%1,%2,%3}, {%4,%5,%6,%7}, {%8,%9}, {%0,%1,%2,%3};"
        : "+f"(d[0]), "+f"(d[1]), "+f"(d[2]), "+f"(d[3])
        : "r"(a[0]), "r"(a[1]), "r"(a[2]), "r"(a[3]), "r"(b[0]), "r"(b[1]));
}
__device__ __forceinline__ uint32_t smem_u32(const void* p) {
    uint32_t a;
    asm("{ .reg .u64 t; cvta.to.shared.u64 t, %1; cvt.u32.u64 %0, t; }"
        : "=r"(a) : "l"(p));
    return a;
}
__device__ __forceinline__ uint32_t packbf(float x, float y) {
    __nv_bfloat162 t = __floats2bfloat162_rn(x, y);
    return *(uint32_t*)&t;
}

__global__ __launch_bounds__(256)
void k_gemm_mma(const float* __restrict__ A,
                const __nv_bfloat16* __restrict__ Wh,
                const __nv_bfloat16* __restrict__ Wl,
                const float* __restrict__ bias,
                float* __restrict__ C) {
    __shared__ __align__(16) __nv_bfloat16 sAh[BM * PADK];
    __shared__ __align__(16) __nv_bfloat16 sAl[BM * PADK];
    __shared__ __align__(16) __nv_bfloat16 sBh[BNT * PADK];
    __shared__ __align__(16) __nv_bfloat16 sBl[BNT * PADK];

    const int tid = threadIdx.x;
    const int wid = tid >> 5;
    const int lane = tid & 31;
    const int bm = blockIdx.x * BM;
    const int bn = blockIdx.y * BNT;
    const int wm = (wid & 1) * 64;
    const int wn = (wid >> 1) * 32;

    const uint32_t uAh = smem_u32(sAh), uAl = smem_u32(sAl);
    const uint32_t uBh = smem_u32(sBh), uBl = smem_u32(sBl);

    float acc[4][4][4];
#pragma unroll
    for (int i = 0; i < 4; i++)
#pragma unroll
        for (int j = 0; j < 4; j++)
#pragma unroll
            for (int f = 0; f < 4; f++) acc[i][j][f] = 0.f;

    // prefetch registers
    float4 fa[4];
    uint4 pwh[2], pwl[2];

    // ---- load chunk 0 ----
#pragma unroll
    for (int j = 0; j < 4; j++) {
        int lin = tid + j * 256;
        int r = lin >> 3, kc = (lin & 7) << 2;
        int grow = bm + r;
        fa[j] = (grow < NN) ? *(const float4*)(A + (size_t)grow * HH + kc)
                            : make_float4(0.f, 0.f, 0.f, 0.f);
    }
#pragma unroll
    for (int j = 0; j < 2; j++) {
        int lin = tid + j * 256;
        int r = lin >> 2, c8 = (lin & 3) << 3;
        size_t g = (size_t)(bn + r) * HH + c8;
        pwh[j] = *(const uint4*)(Wh + g);
        pwl[j] = *(const uint4*)(Wl + g);
    }

    for (int s = 0; s < NCHUNK; s++) {
        // ---- store prefetched regs -> smem (convert A to hi/lo) ----
#pragma unroll
        for (int j = 0; j < 4; j++) {
            int lin = tid + j * 256;
            int r = lin >> 3, kc = (lin & 7) << 2;
            float4 v = fa[j];
            __nv_bfloat16 h0 = __float2bfloat16(v.x), h1 = __float2bfloat16(v.y);
            __nv_bfloat16 h2 = __float2bfloat16(v.z), h3 = __float2bfloat16(v.w);
            uint2 hp, lp;
            hp.x = ((uint32_t)__bfloat16_as_ushort(h0)) |
                   ((uint32_t)__bfloat16_as_ushort(h1) << 16);
            hp.y = ((uint32_t)__bfloat16_as_ushort(h2)) |
                   ((uint32_t)__bfloat16_as_ushort(h3) << 16);
            lp.x = packbf(v.x - __bfloat162float(h0), v.y - __bfloat162float(h1));
            lp.y = packbf(v.z - __bfloat162float(h2), v.w - __bfloat162float(h3));
            *(uint2*)(sAh + r * PADK + kc) = hp;
            *(uint2*)(sAl + r * PADK + kc) = lp;
        }
#pragma unroll
        for (int j = 0; j < 2; j++) {
            int lin = tid + j * 256;
            int r = lin >> 2, c8 = (lin & 3) << 3;
            *(uint4*)(sBh + r * PADK + c8) = pwh[j];
            *(uint4*)(sBl + r * PADK + c8) = pwl[j];
        }
        __syncthreads();

        // ---- prefetch next chunk ----
        if (s + 1 < NCHUNK) {
            int k0n = (s + 1) * BK;
#pragma unroll
            for (int j = 0; j < 4; j++) {
                int lin = tid + j * 256;
                int r = lin >> 3, kc = (lin & 7) << 2;
                int grow = bm + r;
                fa[j] = (grow < NN)
                            ? *(const float4*)(A + (size_t)grow * HH + k0n + kc)
                            : make_float4(0.f, 0.f, 0.f, 0.f);
            }
#pragma unroll
            for (int j = 0; j < 2; j++) {
                int lin = tid + j * 256;
                int r = lin >> 2, c8 = (lin & 3) << 3;
                size_t g = (size_t)(bn + r) * HH + k0n + c8;
                pwh[j] = *(const uint4*)(Wh + g);
                pwl[j] = *(const uint4*)(Wl + g);
            }
        }

        // ---- compute chunk (2 k-steps of 16) ----
#pragma unroll
        for (int ks = 0; ks < 2; ks++) {
            const int k0 = ks * 16;
            const uint32_t lrow = (lane & 15);
            const uint32_t lk = (lane >> 4) * 8;

            uint32_t bh[4][2], bl[4][2];
#pragma unroll
            for (int p = 0; p < 2; p++) {
                uint32_t off = ((wn + p * 16 + lrow) * PADK + k0 + lk) * 2;
                uint32_t t[4];
                ldsm_x4(t, uBh + off);
                bh[p * 2 + 0][0] = t[0]; bh[p * 2 + 0][1] = t[2];
                bh[p * 2 + 1][0] = t[1]; bh[p * 2 + 1][1] = t[3];
                ldsm_x4(t, uBl + off);
                bl[p * 2 + 0][0] = t[0]; bl[p * 2 + 0][1] = t[2];
                bl[p * 2 + 1][0] = t[1]; bl[p * 2 + 1][1] = t[3];
            }
#pragma unroll
            for (int mi = 0; mi < 4; mi++) {
                uint32_t off = ((wm + mi * 16 + lrow) * PADK + k0 + lk) * 2;
                uint32_t ah[4], al[4];
                ldsm_x4(ah, uAh + off);
                ldsm_x4(al, uAl + off);
#pragma unroll
                for (int ni = 0; ni < 4; ni++) {
                    mma_bf16(acc[mi][ni], ah, bh[ni]);
                    mma_bf16(acc[mi][ni], ah, bl[ni]);
                    mma_bf16(acc[mi][ni], al, bh[ni]);
                }
            }
        }
        __syncthreads();
    }

    // ---- epilogue ----
#pragma unroll
    for (int mi = 0; mi < 4; mi++) {
#pragma unroll
        for (int ni = 0; ni < 4; ni++) {
            int row0 = bm + wm + mi * 16 + (lane >> 2);
            int col = bn + wn + ni * 8 + (lane & 3) * 2;
            float b0 = bias ? bias[col] : 0.f;
            float b1 = bias ? bias[col + 1] : 0.f;
            if (row0 < NN) {
                float2 o = make_float2(acc[mi][ni][0] + b0, acc[mi][ni][1] + b1);
                *(float2*)(C + (size_t)row0 * HH + col) = o;
            }
            int row1 = row0 + 8;
            if (row1 < NN) {
                float2 o = make_float2(acc[mi][ni][2] + b0, acc[mi][ni][3] + b1);
                *(float2*)(C + (size_t)row1 * HH + col) = o;
            }
        }
    }
}

// ---------------- aggregation ----------------
__global__ void k_agg_init(const float4* __restrict__ B4, float4* __restrict__ A4,
                           const float4* __restrict__ bc4) {
    int i = blockIdx.x * blockDim.x + threadIdx.x;
    if (i >= NN * (HH / 4)) return;
    int row = i / (HH / 4);
    int c = i & (HH / 4 - 1);
    float d = g_dinv[row];
    d = d * d;
    float4 v = B4[i];
    float4 b = bc4[c];
    float4 o;
    o.x = fmaf(d, v.x, b.x);
    o.y = fmaf(d, v.y, b.y);
    o.z = fmaf(d, v.z, b.z);
    o.w = fmaf(d, v.w, b.w);
    A4[i] = o;
}

__global__ void k_scatter(const int* __restrict__ ei, const float* __restrict__ B,
                          float* __restrict__ A) {
    int g = blockIdx.x * blockDim.x + threadIdx.x;
    if (g >= EE * (HH / 4)) return;
    int e = g >> 7;
    int j = (g & 127) << 2;
    int is64 = g_is64;
    int src = is64 ? ei[2 * e] : ei[e];
    int dst = is64 ? ei[2 * EE + 2 * e] : ei[EE + e];
    float w = g_dinv[src] * g_dinv[dst];
    float4 v = *(const float4*)(B + (size_t)src * HH + j);
    float* out = A + (size_t)dst * HH + j;
    asm volatile("red.global.add.v4.f32 [%0], {%1, %2, %3, %4};"
                 :: "l"(out), "f"(w * v.x), "f"(w * v.y), "f"(w * v.z),
                    "f"(w * v.w)
                 : "memory");
}

// ---------------- batchnorm ----------------
__global__ void k_bnzero() {
    int i = threadIdx.x;
    g_colsum[i] = 0.f;
    g_colsq[i] = 0.f;
}

__global__ void k_bn_stats(const float* __restrict__ A) {
    int c = threadIdx.x;
    float s0 = 0.f, q0 = 0.f, s1 = 0.f, q1 = 0.f;
    for (int r = blockIdx.x; r < NN; r += gridDim.x) {
        const float* row = A + (size_t)r * HH;
        float v0 = row[c];
        float v1 = row[c + 256];
        s0 += v0; q0 += v0 * v0;
        s1 += v1; q1 += v1 * v1;
    }
    atomicAdd(&g_colsum[c], s0);
    atomicAdd(&g_colsq[c], q0);
    atomicAdd(&g_colsum[c + 256], s1);
    atomicAdd(&g_colsq[c + 256], q1);
}

__global__ void k_bn_final(const float* __restrict__ gamma,
                           const float* __restrict__ beta) {
    int c = threadIdx.x;
    float inv_n = 1.0f / (float)NN;
    float mean = g_colsum[c] * inv_n;
    float var = g_colsq[c] * inv_n - mean * mean;
    float sc = gamma[c] * rsqrtf(var + BN_EPS);
    g_scale[c] = sc;
    g_shift[c] = beta[c] - mean * sc;
}

__global__ void k_bn_apply(float4* __restrict__ A4) {
    int i = blockIdx.x * blockDim.x + threadIdx.x;
    if (i >= NN * (HH / 4)) return;
    int c = (i & (HH / 4 - 1)) << 2;
    float4 v = A4[i];
    float x0 = g_scale[c + 0] * v.x + g_shift[c + 0];
    float x1 = g_scale[c + 1] * v.y + g_shift[c + 1];
    float x2 = g_scale[c + 2] * v.z + g_shift[c + 2];
    float x3 = g_scale[c + 3] * v.w + g_shift[c + 3];
    v.x = (x0 >= 0.f) ? x0 : SLOPE * x0;
    v.y = (x1 >= 0.f) ? x1 : SLOPE * x1;
    v.z = (x2 >= 0.f) ? x2 : SLOPE * x2;
    v.w = (x3 >= 0.f) ? x3 : SLOPE * x3;
    A4[i] = v;
}

// ---------------- fused tail ----------------
__global__ void k_weff(const float* __restrict__ W2, const float* __restrict__ b2,
                       const float* __restrict__ WO, const float* __restrict__ bO) {
    int b = blockIdx.x;
    const float* rowp = (b < HH) ? (W2 + (size_t)b * HH) : b2;
    float s = 0.f;
    for (int j = threadIdx.x; j < HH; j += 256) s += rowp[j] * WO[j];
#pragma unroll
    for (int o = 16; o; o >>= 1) s += __shfl_xor_sync(0xffffffffu, s, o);
    __shared__ float red[8];
    if ((threadIdx.x & 31) == 0) red[threadIdx.x >> 5] = s;
    __syncthreads();
    if (threadIdx.x == 0) {
        float t = 0.f;
        for (int i = 0; i < 8; i++) t += red[i];
        g_weff[b] = (b < HH) ? t : (t + bO[0]);
    }
}

__global__ void k_out(const float* __restrict__ A, float* __restrict__ out) {
    int w = (blockIdx.x * blockDim.x + threadIdx.x) >> 5;
    int lane = threadIdx.x & 31;
    if (w >= NN) return;
    const float4* row = (const float4*)(A + (size_t)w * HH);
    const float4* wf = (const float4*)g_weff;
    float s = 0.f;
#pragma unroll
    for (int i = 0; i < 4; i++) {
        float4 a = row[lane + 32 * i];
        float4 b = wf[lane + 32 * i];
        s += a.x * b.x + a.y * b.y + a.z * b.z + a.w * b.w;
    }
#pragma unroll
    for (int o = 16; o; o >>= 1) s += __shfl_xor_sync(0xffffffffu, s, o);
    if (lane == 0) {
        float t = s + g_weff[HH];
        out[w] = 1.0f / (1.0f + expf(-t));
    }
}

// ---------------- launcher ----------------
extern "C" void kernel_launch(void* const* d_in, const int* in_sizes, int n_in,
                              void* d_out, int out_size) {
    const float* x     = (const float*)d_in[0];
    const int*   ei    = (const int*)d_in[1];
    const float* W1    = (const float*)d_in[2];
    const float* b1    = (const float*)d_in[3];
    const float* Wc    = (const float*)d_in[4];
    const float* bc    = (const float*)d_in[5];
    const float* gamma = (const float*)d_in[6];
    const float* beta  = (const float*)d_in[7];
    const float* W2    = (const float*)d_in[8];
    const float* b2    = (const float*)d_in[9];
    const float* WO    = (const float*)d_in[10];
    const float* bO    = (const float*)d_in[11];
    float* out = (float*)d_out;

    float *pA, *pB;
    cudaGetSymbolAddress((void**)&pA, g_A);
    cudaGetSymbolAddress((void**)&pB, g_B);
    __nv_bfloat16 *w1h, *w1l, *wch, *wcl;
    cudaGetSymbolAddress((void**)&w1h, g_w1h);
    cudaGetSymbolAddress((void**)&w1l, g_w1l);
    cudaGetSymbolAddress((void**)&wch, g_wch);
    cudaGetSymbolAddress((void**)&wcl, g_wcl);

    k_prep<<<(NN + 255) / 256, 256>>>(ei);
    k_deg<<<(EE + 255) / 256, 256>>>(ei);
    k_dinv<<<(NN + 255) / 256, 256>>>();
    k_conv_w<<<HH, 256>>>(W1, w1h, w1l);
    k_conv_w<<<HH, 256>>>(Wc, wch, wcl);

    dim3 gg((NN + BM - 1) / BM, HH / BNT);   // (782, 4)
    // h = x @ W1 + b1
    k_gemm_mma<<<gg, 256>>>(x, w1h, w1l, b1, pA);

    const int elem4 = NN * (HH / 4);
    const int edge4 = EE * (HH / 4);
    for (int layer = 0; layer < 2; layer++) {
        k_gemm_mma<<<gg, 256>>>(pA, wch, wcl, nullptr, pB);
        k_agg_init<<<(elem4 + 255) / 256, 256>>>(
            (const float4*)pB, (float4*)pA, (const float4*)bc);
        k_scatter<<<(edge4 + 255) / 256, 256>>>(ei, pB, pA);
        k_bnzero<<<1, 512>>>();
        k_bn_stats<<<2048, 256>>>(pA);
        k_bn_final<<<1, 512>>>(gamma, beta);
        k_bn_apply<<<(elem4 + 255) / 256, 256>>>((float4*)pA);
    }

    k_weff<<<HH + 1, 256>>>(W2, b2, WO, bO);
    k_out<<<(NN * 32 + 255) / 256, 256>>>(pA, out);
}